// round 11
// baseline (speedup 1.0000x reference)
#include <cuda_runtime.h>
#include <cuda_bf16.h>
#include <math.h>
#include <stdint.h>

#define NB   2
#define C    256
#define H    64
#define W    64
#define HW   4096
#define M    8192
#define G    8
#define P    9
#define CG   32
#define OMC  216

typedef __nv_bfloat16 bf16;

// ---- scratch (device globals) ----
__device__ __align__(16) bf16 g_xh[M * C];
__device__ __align__(16) bf16 g_xl[M * C];
__device__ __align__(16) bf16 g_yh[M * C];
__device__ __align__(16) bf16 g_yl[M * C];
__device__ __align__(16) bf16 g_zh[M * C];
__device__ __align__(16) bf16 g_zl[M * C];
__device__ __align__(16) bf16 g_sh[M * C];
__device__ __align__(16) bf16 g_sl[M * C];
__device__ __align__(16) float g_xproj[M * C];
__device__ __align__(16) float g_om[M * OMC];
// weight planes, all [n-row][k] k-contig, 256x256
__device__ __align__(16) bf16 g_wch[C * C], g_wcl[C * C];   // conv1
__device__ __align__(16) bf16 g_wih[C * C], g_wil[C * C];   // inproj
__device__ __align__(16) bf16 g_woh[C * C], g_wol[C * C];   // outproj
__device__ __align__(16) bf16 g_wmh[C * C], g_wml[C * C];   // off|mask

__device__ __forceinline__ float silu(float t) { return t / (1.f + __expf(-t)); }

__device__ __forceinline__ uint32_t smem_u32_of(const void* p) {
    uint32_t a;
    asm("{ .reg .u64 t; cvta.to.shared.u64 t, %1; cvt.u32.u64 %0, t; }"
        : "=r"(a) : "l"(p));
    return a;
}
__device__ __forceinline__ void split1(float v, bf16& hi, bf16& lo) {
    hi = __float2bfloat16(v);
    lo = __float2bfloat16(v - __bfloat162float(hi));
}
__device__ __forceinline__ void ldsm4(uint32_t* r, uint32_t addr) {
    asm volatile("ldmatrix.sync.aligned.m8n8.x4.shared.b16 {%0,%1,%2,%3}, [%4];"
                 : "=r"(r[0]), "=r"(r[1]), "=r"(r[2]), "=r"(r[3]) : "r"(addr));
}
__device__ __forceinline__ void mma16816(float* c, const uint32_t* a, uint32_t b0, uint32_t b1) {
    asm volatile(
        "mma.sync.aligned.m16n8k16.row.col.f32.bf16.bf16.f32 "
        "{%0,%1,%2,%3}, {%4,%5,%6,%7}, {%8,%9}, {%0,%1,%2,%3};"
        : "+f"(c[0]), "+f"(c[1]), "+f"(c[2]), "+f"(c[3])
        : "r"(a[0]), "r"(a[1]), "r"(a[2]), "r"(a[3]), "r"(b0), "r"(b1));
}
__device__ __forceinline__ void cp16(uint32_t dst, const void* src) {
    asm volatile("cp.async.cg.shared.global [%0], [%1], 16;" :: "r"(dst), "l"(src));
}
__device__ __forceinline__ void cp_commit() {
    asm volatile("cp.async.commit_group;");
}
template<int N> __device__ __forceinline__ void cp_wait() {
    asm volatile("cp.async.wait_group %0;" :: "n"(N));
}

// SMEM: per stage bf16 planes, 80B padded rows (conflict-free ldmatrix).
// A: 64 rows (hi/lo), B: 128 rows (hi/lo)   (R9-proven geometry)
#define ROWB      80
#define OFF_AHI   0
#define OFF_ALO   (64 * ROWB)
#define OFF_BHI   (128 * ROWB)
#define OFF_BLO   (256 * ROWB)
#define STAGE_SZ  (384 * ROWB)          // 30720
#define SMEM_TOTAL (2 * STAGE_SZ)       // 61440

union pk8 { bf16 h[8]; uint4 u; };

// ---------------------------------------------------------------------------
// merged prep: blocks [0,512) = x NCHW->NHWC planes;
// [512,768) conv1 rows; [768,1024) off|mask rows;
// [1024,1040) inproj transpose tiles; [1040,1056) outproj tiles.
// ---------------------------------------------------------------------------
__global__ __launch_bounds__(256) void prep_fused(
    const float* __restrict__ x,
    const float* __restrict__ conv1w,
    const float* __restrict__ offw, const float* __restrict__ maskw,
    const float* __restrict__ inw,  const float* __restrict__ outw,
    bf16* __restrict__ xh, bf16* __restrict__ xl,
    bf16* __restrict__ wch, bf16* __restrict__ wcl,
    bf16* __restrict__ wmh, bf16* __restrict__ wml,
    bf16* __restrict__ wih, bf16* __restrict__ wil,
    bf16* __restrict__ woh, bf16* __restrict__ wol)
{
    __shared__ float t[64][65];
    const int b = blockIdx.x;
    const int tid = threadIdx.x;

    if (b < 512) {
        // prep_x: hw0 = (b&63)*64, c0 = ((b>>6)&3)*64, n = b>>8
        const int hw0 = (b & 63) * 64, c0 = ((b >> 6) & 3) * 64, n = b >> 8;
        #pragma unroll
        for (int r = 0; r < 4; r++) {
            int c = (tid >> 4) + r * 16;
            float4 v = *(const float4*)&x[((size_t)n * C + c0 + c) * HW + hw0 + (tid & 15) * 4];
            t[c][(tid & 15) * 4 + 0] = v.x;
            t[c][(tid & 15) * 4 + 1] = v.y;
            t[c][(tid & 15) * 4 + 2] = v.z;
            t[c][(tid & 15) * 4 + 3] = v.w;
        }
        __syncthreads();
        const int hwl = tid >> 2, cq = (tid & 3) * 16;
        pk8 hb[2], lb[2];
        #pragma unroll
        for (int j = 0; j < 16; j++)
            split1(t[cq + j][hwl], hb[j >> 3].h[j & 7], lb[j >> 3].h[j & 7]);
        size_t base = ((size_t)n * HW + hw0 + hwl) * C + c0 + cq;
        *(uint4*)&xh[base] = hb[0].u; *(uint4*)&xh[base + 8] = hb[1].u;
        *(uint4*)&xl[base] = lb[0].u; *(uint4*)&xl[base + 8] = lb[1].u;
        return;
    }
    if (b < 768) {
        int row = b - 512;
        bf16 hh, ll; split1(conv1w[(size_t)row * C + tid], hh, ll);
        wch[(size_t)row * C + tid] = hh;
        wcl[(size_t)row * C + tid] = ll;
        return;
    }
    if (b < 1024) {
        int nrow = b - 768;
        float v = 0.f;
        if (nrow < 144)      v = offw[(size_t)tid * 144 + nrow];
        else if (nrow < 216) v = maskw[(size_t)tid * 72 + nrow - 144];
        bf16 hh, ll; split1(v, hh, ll);
        wmh[(size_t)nrow * C + tid] = hh;
        wml[(size_t)nrow * C + tid] = ll;
        return;
    }
    const float* Wk = (b < 1040) ? inw : outw;
    bf16* hi = (b < 1040) ? wih : woh;
    bf16* lo = (b < 1040) ? wil : wol;
    const int t4 = (b - 1024) & 15;
    const int k0 = (t4 & 3) * 64, n0 = (t4 >> 2) * 64;
    #pragma unroll
    for (int r = 0; r < 4; r++) {
        int k = k0 + (tid >> 4) + r * 16;
        float4 v = *(const float4*)&Wk[(size_t)k * C + n0 + (tid & 15) * 4];
        t[(tid & 15) * 4 + 0][k - k0] = v.x;
        t[(tid & 15) * 4 + 1][k - k0] = v.y;
        t[(tid & 15) * 4 + 2][k - k0] = v.z;
        t[(tid & 15) * 4 + 3][k - k0] = v.w;
    }
    __syncthreads();
    const int nl = tid >> 2, kq = (tid & 3) * 16;
    pk8 hb[2], lb[2];
    #pragma unroll
    for (int j = 0; j < 16; j++)
        split1(t[nl][kq + j], hb[j >> 3].h[j & 7], lb[j >> 3].h[j & 7]);
    size_t base = (size_t)(n0 + nl) * C + k0 + kq;
    *(uint4*)&hi[base] = hb[0].u; *(uint4*)&hi[base + 8] = hb[1].u;
    *(uint4*)&lo[base] = lb[0].u; *(uint4*)&lo[base + 8] = lb[1].u;
}

// ---------------------------------------------------------------------------
// GEMM body (R9-proven): 64(M) x 128(N) x 32(BK), 8 chunks, 8 warps 2x4.
// ---------------------------------------------------------------------------
template<int MODE>
__device__ __forceinline__ void gemm_body(
    int bo, int bp,
    const bf16* __restrict__ Ah, const bf16* __restrict__ Al,
    const bf16* __restrict__ Bh, const bf16* __restrict__ Bl,
    const float* __restrict__ bias0, const float* __restrict__ bias1,
    const float* __restrict__ bg, const float* __restrict__ bb,
    const float* __restrict__ bm, const float* __restrict__ bv,
    float* __restrict__ outF, bf16* __restrict__ outHi, bf16* __restrict__ outLo)
{
    extern __shared__ char smem[];
    const uint32_t sb = smem_u32_of(smem);
    const int tid = threadIdx.x;
    const int lane = tid & 31, wid = tid >> 5;
    const int warpM = wid >> 2, warpN = wid & 3;

    auto issue = [&](int s, int chk) {
        const int c0b = chk * 64;
        const uint32_t stg = sb + s * STAGE_SZ;
        #pragma unroll
        for (int i = 0; i < 6; i++) {
            int id = tid + 256 * i;
            if (id < 512) {
                int pl = id >> 8, rem = id & 255, row = rem >> 2, q = rem & 3;
                const char* src = (const char*)(pl ? Al : Ah)
                                  + ((size_t)(bp + row) * C) * 2 + c0b + q * 16;
                cp16(stg + (pl ? OFF_ALO : OFF_AHI) + row * ROWB + q * 16, src);
            } else {
                int id2 = id - 512;
                int pl = id2 >> 9, rem = id2 & 511, row = rem >> 2, q = rem & 3;
                const char* src = (const char*)(pl ? Bl : Bh)
                                  + ((size_t)(bo + row) * C) * 2 + c0b + q * 16;
                cp16(stg + (pl ? OFF_BLO : OFF_BHI) + row * ROWB + q * 16, src);
            }
        }
        cp_commit();
    };

    float acc[2][4][4];
    #pragma unroll
    for (int mt = 0; mt < 2; mt++)
        #pragma unroll
        for (int nt = 0; nt < 4; nt++)
            #pragma unroll
            for (int q = 0; q < 4; q++) acc[mt][nt][q] = 0.f;

    const int lrow = lane & 15;
    const int lhalf = (lane >> 4) * 16;

    issue(0, 0);
    #pragma unroll 1
    for (int chk = 0; chk < 8; chk++) {
        if (chk < 7) { issue((chk + 1) & 1, chk + 1); cp_wait<1>(); }
        else         { cp_wait<0>(); }
        __syncthreads();
        const uint32_t stg = sb + (chk & 1) * STAGE_SZ;
        #pragma unroll
        for (int ks = 0; ks < 2; ks++) {
            const uint32_t kb = ks * 32 + lhalf;
            uint32_t aH[2][4], aL[2][4], bH[2][4], bL[2][4];
            #pragma unroll
            for (int mt = 0; mt < 2; mt++) {
                uint32_t r = (warpM * 32 + mt * 16 + lrow) * ROWB + kb;
                ldsm4(aH[mt], stg + OFF_AHI + r);
                ldsm4(aL[mt], stg + OFF_ALO + r);
            }
            #pragma unroll
            for (int ng = 0; ng < 2; ng++) {
                uint32_t r = (warpN * 32 + ng * 16 + lrow) * ROWB + kb;
                ldsm4(bH[ng], stg + OFF_BHI + r);
                ldsm4(bL[ng], stg + OFF_BLO + r);
            }
            #pragma unroll
            for (int mt = 0; mt < 2; mt++)
                #pragma unroll
                for (int nt = 0; nt < 4; nt++) {
                    const int ng = nt >> 1, hsel = nt & 1;
                    mma16816(acc[mt][nt], aH[mt], bH[ng][hsel], bH[ng][2 + hsel]);
                    mma16816(acc[mt][nt], aH[mt], bL[ng][hsel], bL[ng][2 + hsel]);
                    mma16816(acc[mt][nt], aL[mt], bH[ng][hsel], bH[ng][2 + hsel]);
                }
        }
        __syncthreads();
    }

    const int rql = lane >> 2;
    const int cql = (lane & 3) * 2;

    if (MODE == 0) {
        #pragma unroll
        for (int mt = 0; mt < 2; mt++) {
            int p0 = bp + warpM * 32 + mt * 16 + rql;
            #pragma unroll
            for (int nt = 0; nt < 4; nt++) {
                int o = bo + warpN * 32 + nt * 8 + cql;
                float s0 = bg[o] * rsqrtf(bv[o] + 1e-3f);
                float s1 = bg[o+1] * rsqrtf(bv[o+1] + 1e-3f);
                float b0 = bb[o] - bm[o] * s0;
                float b1 = bb[o+1] - bm[o+1] * s1;
                float e0 = silu(acc[mt][nt][0] * s0 + b0);
                float e1 = silu(acc[mt][nt][1] * s1 + b1);
                float e2 = silu(acc[mt][nt][2] * s0 + b0);
                float e3 = silu(acc[mt][nt][3] * s1 + b1);
                __nv_bfloat162 h01, l01, h23, l23;
                split1(e0, h01.x, l01.x); split1(e1, h01.y, l01.y);
                split1(e2, h23.x, l23.x); split1(e3, h23.y, l23.y);
                *(__nv_bfloat162*)&outHi[(size_t)p0 * C + o] = h01;
                *(__nv_bfloat162*)&outLo[(size_t)p0 * C + o] = l01;
                *(__nv_bfloat162*)&outHi[(size_t)(p0 + 8) * C + o] = h23;
                *(__nv_bfloat162*)&outLo[(size_t)(p0 + 8) * C + o] = l23;
            }
        }
    } else if (MODE == 1) {
        #pragma unroll
        for (int mt = 0; mt < 2; mt++) {
            int p0 = bp + warpM * 32 + mt * 16 + rql;
            #pragma unroll
            for (int nt = 0; nt < 4; nt++) {
                int o = bo + warpN * 32 + nt * 8 + cql;
                float b0 = bias0[o], b1 = bias0[o + 1];
                *(float2*)&outF[(size_t)p0 * C + o] =
                    make_float2(acc[mt][nt][0] + b0, acc[mt][nt][1] + b1);
                *(float2*)&outF[(size_t)(p0 + 8) * C + o] =
                    make_float2(acc[mt][nt][2] + b0, acc[mt][nt][3] + b1);
            }
        }
    } else if (MODE == 2) {
        #pragma unroll
        for (int mt = 0; mt < 2; mt++) {
            int p0 = bp + warpM * 32 + mt * 16 + rql;
            #pragma unroll
            for (int nt = 0; nt < 4; nt++) {
                int o = bo + warpN * 32 + nt * 8 + cql;
                #pragma unroll
                for (int j = 0; j < 2; j++) {
                    int col = o + j;
                    if (col < OMC) {
                        float bi = (col < 144) ? bias0[col] : bias1[col - 144];
                        outF[(size_t)p0 * OMC + col]       = acc[mt][nt][j] + bi;
                        outF[(size_t)(p0 + 8) * OMC + col] = acc[mt][nt][2 + j] + bi;
                    }
                }
            }
        }
    } else {
        float* ts = (float*)smem;          // [128 o][68 p]
        #pragma unroll
        for (int mt = 0; mt < 2; mt++) {
            int r0 = warpM * 32 + mt * 16 + rql;
            #pragma unroll
            for (int nt = 0; nt < 4; nt++) {
                int c0t = warpN * 32 + nt * 8 + cql;
                ts[(size_t)c0t * 68 + r0]           = acc[mt][nt][0];
                ts[(size_t)(c0t + 1) * 68 + r0]     = acc[mt][nt][1];
                ts[(size_t)c0t * 68 + r0 + 8]       = acc[mt][nt][2];
                ts[(size_t)(c0t + 1) * 68 + r0 + 8] = acc[mt][nt][3];
            }
        }
        __syncthreads();
        const int n = bp >> 12, hwbase = bp & 4095;
        const int ol = tid >> 1, ph = (tid & 1) * 32;
        const int o = bo + ol;
        float sc = bg[o] * rsqrtf(bv[o] + 1e-5f);
        float bi = bb[o] - bm[o] * sc + bias0[o] * sc;
        float* op = &outF[((size_t)(n * C + o)) * HW + hwbase + ph];
        #pragma unroll
        for (int q = 0; q < 8; q++) {
            float v0 = silu(ts[(size_t)ol * 68 + ph + q * 4 + 0] * sc + bi);
            float v1 = silu(ts[(size_t)ol * 68 + ph + q * 4 + 1] * sc + bi);
            float v2 = silu(ts[(size_t)ol * 68 + ph + q * 4 + 2] * sc + bi);
            float v3 = silu(ts[(size_t)ol * 68 + ph + q * 4 + 3] * sc + bi);
            *(float4*)&op[q * 4] = make_float4(v0, v1, v2, v3);
        }
    }
}

template<int MODE>
__global__ __launch_bounds__(256, 2)
void gemm_p(const bf16* __restrict__ Ah, const bf16* __restrict__ Al,
            const bf16* __restrict__ Bh, const bf16* __restrict__ Bl,
            const float* __restrict__ bias0, const float* __restrict__ bias1,
            const float* __restrict__ bg, const float* __restrict__ bb,
            const float* __restrict__ bm, const float* __restrict__ bv,
            float* __restrict__ outF, bf16* __restrict__ outHi, bf16* __restrict__ outLo)
{
    gemm_body<MODE>(blockIdx.x * 128, blockIdx.y * 64,
                    Ah, Al, Bh, Bl, bias0, bias1, bg, bb, bm, bv,
                    outF, outHi, outLo);
}

// ---------------------------------------------------------------------------
// dwln body (v1 proven): one block per pixel; depthwise 3x3 + LN + GELU
// ---------------------------------------------------------------------------
__device__ __forceinline__ void dwln_body(
    int p,
    const bf16* __restrict__ yh, const bf16* __restrict__ yl,
    const float* __restrict__ dww, const float* __restrict__ dwb,
    const float* __restrict__ lng, const float* __restrict__ lnb,
    bf16* __restrict__ zh, bf16* __restrict__ zl)
{
    const int c = threadIdx.x;
    const int n = p >> 12, hw = p & 4095;
    const int h = hw >> 6, w = hw & 63;

    float acc = dwb[c];
    #pragma unroll
    for (int ky = 0; ky < 3; ky++) {
        int hh = h + ky - 1;
        if (hh < 0 || hh > 63) continue;
        #pragma unroll
        for (int kx = 0; kx < 3; kx++) {
            int ww = w + kx - 1;
            if (ww < 0 || ww > 63) continue;
            size_t idx = ((size_t)(n << 12) + (hh << 6) + ww) * C + c;
            float v = __bfloat162float(yh[idx]) + __bfloat162float(yl[idx]);
            acc += v * dww[c * 9 + ky * 3 + kx];
        }
    }
    float s1 = acc, s2 = acc * acc;
    #pragma unroll
    for (int o = 16; o; o >>= 1) {
        s1 += __shfl_xor_sync(0xffffffffu, s1, o);
        s2 += __shfl_xor_sync(0xffffffffu, s2, o);
    }
    __shared__ float w1[8], w2[8];
    int warp = c >> 5, lane = c & 31;
    if (lane == 0) { w1[warp] = s1; w2[warp] = s2; }
    __syncthreads();
    if (warp == 0) {
        float a = lane < 8 ? w1[lane] : 0.f;
        float b = lane < 8 ? w2[lane] : 0.f;
        #pragma unroll
        for (int o = 4; o; o >>= 1) {
            a += __shfl_xor_sync(0xffffffffu, a, o);
            b += __shfl_xor_sync(0xffffffffu, b, o);
        }
        if (lane == 0) { w1[0] = a; w2[0] = b; }
    }
    __syncthreads();
    float mu = w1[0] * (1.f / 256.f);
    float var = w2[0] * (1.f / 256.f) - mu * mu;
    float zn = (acc - mu) * rsqrtf(var + 1e-5f) * lng[c] + lnb[c];
    float gl = 0.5f * zn * (1.f + erff(zn * 0.70710678118654752f));
    bf16 hh2, ll2; split1(gl, hh2, ll2);
    zh[(size_t)p * C + c] = hh2;
    zl[(size_t)p * C + c] = ll2;
}

// ---------------------------------------------------------------------------
// fused launch: blocks [0,256) = inproj GEMM (MODE 1); [256, 256+8192) = dwln
// ---------------------------------------------------------------------------
__global__ __launch_bounds__(256, 2)
void fused_g1_dwln(
    const bf16* __restrict__ yh, const bf16* __restrict__ yl,
    const bf16* __restrict__ wih, const bf16* __restrict__ wil,
    const float* __restrict__ inproj_b,
    float* __restrict__ xproj,
    const float* __restrict__ dww, const float* __restrict__ dwb,
    const float* __restrict__ lng, const float* __restrict__ lnb,
    bf16* __restrict__ zh, bf16* __restrict__ zl)
{
    const int b = blockIdx.x;
    if (b < 256) {
        gemm_body<1>((b & 1) * 128, (b >> 1) * 64,
                     yh, yl, wih, wil, inproj_b, nullptr,
                     nullptr, nullptr, nullptr, nullptr,
                     xproj, nullptr, nullptr);
    } else {
        dwln_body(b - 256, yh, yl, dww, dwb, lng, lnb, zh, zl);
    }
}

// ---------------------------------------------------------------------------
// deformable sampling; reads xproj fp32 + om, writes s planes
// ---------------------------------------------------------------------------
__device__ __forceinline__ float samp(const float* __restrict__ xb, int yy, int xx)
{
    if (yy >= 1 && yy <= 64 && xx >= 1 && xx <= 64)
        return xb[((size_t)((yy - 1) << 6) + (xx - 1)) * C];
    return 0.f;
}

__global__ __launch_bounds__(256) void dcn_kernel(
    const float* __restrict__ xproj, const float* __restrict__ om,
    bf16* __restrict__ sh, bf16* __restrict__ sl)
{
    const int p = blockIdx.x;
    const int t = threadIdx.x;
    const int g = t >> 5, lane = t & 31;
    const int n = p >> 12, hw = p & 4095;
    const int h = hw >> 6, w = hw & 63;

    const float* offp = om + (size_t)p * OMC + g * 18;
    const float* mlp  = om + (size_t)p * OMC + 144 + g * 9;

    float ml[9];
    float mx = -1e30f;
    #pragma unroll
    for (int i = 0; i < 9; i++) { ml[i] = mlp[i]; mx = fmaxf(mx, ml[i]); }
    float se = 0.f;
    #pragma unroll
    for (int i = 0; i < 9; i++) { ml[i] = __expf(ml[i] - mx); se += ml[i]; }
    float inv = 1.f / se;

    const int ch = g * 32 + lane;
    const float* xb = xproj + (size_t)n * HW * C + ch;
    float acc = 0.f;
    #pragma unroll
    for (int i = 0; i < 9; i++) {
        float px = (float)w + (float)(i / 3) + offp[2 * i];
        float py = (float)h + (float)(i % 3) + offp[2 * i + 1];
        float x0f = floorf(px), y0f = floorf(py);
        float wx = px - x0f, wy = py - y0f;
        int x0 = (int)x0f, y0 = (int)y0f;
        float v00 = samp(xb, y0,     x0);
        float v10 = samp(xb, y0,     x0 + 1);
        float v01 = samp(xb, y0 + 1, x0);
        float v11 = samp(xb, y0 + 1, x0 + 1);
        float bil = v00 * (1.f - wx) * (1.f - wy) + v10 * wx * (1.f - wy)
                  + v01 * (1.f - wx) * wy         + v11 * wx * wy;
        acc += ml[i] * inv * bil;
    }
    bf16 hh2, ll2; split1(acc, hh2, ll2);
    sh[(size_t)p * C + ch] = hh2;
    sl[(size_t)p * C + ch] = ll2;
}

// ---------------------------------------------------------------------------
extern "C" void kernel_launch(void* const* d_in, const int* in_sizes, int n_in,
                              void* d_out, int out_size)
{
    const float* x        = (const float*)d_in[0];
    const float* conv1_w  = (const float*)d_in[1];
    const float* bn1_g    = (const float*)d_in[2];
    const float* bn1_b    = (const float*)d_in[3];
    const float* bn1_m    = (const float*)d_in[4];
    const float* bn1_v    = (const float*)d_in[5];
    const float* inproj_w = (const float*)d_in[6];
    const float* inproj_b = (const float*)d_in[7];
    const float* dw_w     = (const float*)d_in[8];
    const float* dw_b     = (const float*)d_in[9];
    const float* ln_g     = (const float*)d_in[10];
    const float* ln_b     = (const float*)d_in[11];
    const float* off_w    = (const float*)d_in[12];
    const float* off_b    = (const float*)d_in[13];
    const float* mask_w   = (const float*)d_in[14];
    const float* mask_b   = (const float*)d_in[15];
    const float* outproj_w= (const float*)d_in[16];
    const float* outproj_b= (const float*)d_in[17];
    const float* bn2_g    = (const float*)d_in[18];
    const float* bn2_b    = (const float*)d_in[19];
    const float* bn2_m    = (const float*)d_in[20];
    const float* bn2_v    = (const float*)d_in[21];
    float* out = (float*)d_out;

    bf16 *xh, *xl, *yh, *yl, *zh, *zl, *sh, *sl;
    bf16 *wch, *wcl, *wih, *wil, *woh, *wol, *wmh, *wml;
    float *xproj, *om;
    cudaGetSymbolAddress((void**)&xh, g_xh); cudaGetSymbolAddress((void**)&xl, g_xl);
    cudaGetSymbolAddress((void**)&yh, g_yh); cudaGetSymbolAddress((void**)&yl, g_yl);
    cudaGetSymbolAddress((void**)&zh, g_zh); cudaGetSymbolAddress((void**)&zl, g_zl);
    cudaGetSymbolAddress((void**)&sh, g_sh); cudaGetSymbolAddress((void**)&sl, g_sl);
    cudaGetSymbolAddress((void**)&wch, g_wch); cudaGetSymbolAddress((void**)&wcl, g_wcl);
    cudaGetSymbolAddress((void**)&wih, g_wih); cudaGetSymbolAddress((void**)&wil, g_wil);
    cudaGetSymbolAddress((void**)&woh, g_woh); cudaGetSymbolAddress((void**)&wol, g_wol);
    cudaGetSymbolAddress((void**)&wmh, g_wmh); cudaGetSymbolAddress((void**)&wml, g_wml);
    cudaGetSymbolAddress((void**)&xproj, g_xproj);
    cudaGetSymbolAddress((void**)&om, g_om);

    cudaFuncSetAttribute(gemm_p<0>, cudaFuncAttributeMaxDynamicSharedMemorySize, SMEM_TOTAL);
    cudaFuncSetAttribute(gemm_p<2>, cudaFuncAttributeMaxDynamicSharedMemorySize, SMEM_TOTAL);
    cudaFuncSetAttribute(gemm_p<3>, cudaFuncAttributeMaxDynamicSharedMemorySize, SMEM_TOTAL);
    cudaFuncSetAttribute(fused_g1_dwln, cudaFuncAttributeMaxDynamicSharedMemorySize, SMEM_TOTAL);

    // ---- prep (one launch) ----
    prep_fused<<<1056, 256>>>(x, conv1_w, off_w, mask_w, inproj_w, outproj_w,
                              xh, xl, wch, wcl, wmh, wml, wih, wil, woh, wol);

    dim3 grd(2, 128);
    // ---- pipeline ----
    gemm_p<0><<<grd, 256, SMEM_TOTAL>>>(xh, xl, wch, wcl, nullptr, nullptr,
                                        bn1_g, bn1_b, bn1_m, bn1_v,
                                        nullptr, yh, yl);
    fused_g1_dwln<<<256 + M, 256, SMEM_TOTAL>>>(yh, yl, wih, wil, inproj_b, xproj,
                                                dw_w, dw_b, ln_g, ln_b, zh, zl);
    gemm_p<2><<<grd, 256, SMEM_TOTAL>>>(zh, zl, wmh, wml, off_b, mask_b,
                                        nullptr, nullptr, nullptr, nullptr,
                                        om, nullptr, nullptr);
    dcn_kernel<<<M, 256>>>(xproj, om, sh, sl);
    gemm_p<3><<<grd, 256, SMEM_TOTAL>>>(sh, sl, woh, wol, outproj_b, nullptr,
                                        bn2_g, bn2_b, bn2_m, bn2_v,
                                        out, nullptr, nullptr);
}

// round 12
// speedup vs baseline: 1.1421x; 1.1421x over previous
#include <cuda_runtime.h>
#include <cuda_bf16.h>
#include <cuda_fp16.h>
#include <math.h>
#include <stdint.h>

#define NB   2
#define C    256
#define H    64
#define W    64
#define HW   4096
#define M    8192
#define G    8
#define P    9
#define CG   32
#define OMC  216

typedef __nv_bfloat16 bf16;

// ---- scratch (device globals) ----
__device__ __align__(16) bf16 g_xh[M * C];
__device__ __align__(16) bf16 g_xl[M * C];
__device__ __align__(16) bf16 g_yh[M * C];
__device__ __align__(16) bf16 g_yl[M * C];
__device__ __align__(16) bf16 g_zh[M * C];
__device__ __align__(16) bf16 g_zl[M * C];
__device__ __align__(16) bf16 g_sh[M * C];
__device__ __align__(16) bf16 g_sl[M * C];
__device__ __align__(16) __half g_xproj[M * C];     // fp16 (dcn is L2-BW-bound)
__device__ __align__(16) float g_om[M * OMC];
// weight planes, all [n-row][k] k-contig, 256x256
__device__ __align__(16) bf16 g_wch[C * C], g_wcl[C * C];   // conv1
__device__ __align__(16) bf16 g_wih[C * C], g_wil[C * C];   // inproj
__device__ __align__(16) bf16 g_woh[C * C], g_wol[C * C];   // outproj
__device__ __align__(16) bf16 g_wmh[C * C], g_wml[C * C];   // off|mask

__device__ __forceinline__ float silu(float t) { return t / (1.f + __expf(-t)); }

__device__ __forceinline__ uint32_t smem_u32_of(const void* p) {
    uint32_t a;
    asm("{ .reg .u64 t; cvta.to.shared.u64 t, %1; cvt.u32.u64 %0, t; }"
        : "=r"(a) : "l"(p));
    return a;
}
__device__ __forceinline__ void split1(float v, bf16& hi, bf16& lo) {
    hi = __float2bfloat16(v);
    lo = __float2bfloat16(v - __bfloat162float(hi));
}
__device__ __forceinline__ void ldsm4(uint32_t* r, uint32_t addr) {
    asm volatile("ldmatrix.sync.aligned.m8n8.x4.shared.b16 {%0,%1,%2,%3}, [%4];"
                 : "=r"(r[0]), "=r"(r[1]), "=r"(r[2]), "=r"(r[3]) : "r"(addr));
}
__device__ __forceinline__ void mma16816(float* c, const uint32_t* a, uint32_t b0, uint32_t b1) {
    asm volatile(
        "mma.sync.aligned.m16n8k16.row.col.f32.bf16.bf16.f32 "
        "{%0,%1,%2,%3}, {%4,%5,%6,%7}, {%8,%9}, {%0,%1,%2,%3};"
        : "+f"(c[0]), "+f"(c[1]), "+f"(c[2]), "+f"(c[3])
        : "r"(a[0]), "r"(a[1]), "r"(a[2]), "r"(a[3]), "r"(b0), "r"(b1));
}
__device__ __forceinline__ void cp16(uint32_t dst, const void* src) {
    asm volatile("cp.async.cg.shared.global [%0], [%1], 16;" :: "r"(dst), "l"(src));
}
__device__ __forceinline__ void cp_commit() {
    asm volatile("cp.async.commit_group;");
}
template<int N> __device__ __forceinline__ void cp_wait() {
    asm volatile("cp.async.wait_group %0;" :: "n"(N));
}

// SMEM: per stage bf16 planes, 80B padded rows (conflict-free ldmatrix).
// A: 64 rows (hi/lo), B: 128 rows (hi/lo)   (R9-proven geometry)
#define ROWB      80
#define OFF_AHI   0
#define OFF_ALO   (64 * ROWB)
#define OFF_BHI   (128 * ROWB)
#define OFF_BLO   (256 * ROWB)
#define STAGE_SZ  (384 * ROWB)          // 30720
#define SMEM_TOTAL (2 * STAGE_SZ)       // 61440

union pk8 { bf16 h[8]; uint4 u; };

// ---------------------------------------------------------------------------
// merged prep (R11-verified): blocks [0,512) x planes; [512,768) conv1;
// [768,1024) off|mask; [1024,1040) inproj tiles; [1040,1056) outproj tiles.
// ---------------------------------------------------------------------------
__global__ __launch_bounds__(256) void prep_fused(
    const float* __restrict__ x,
    const float* __restrict__ conv1w,
    const float* __restrict__ offw, const float* __restrict__ maskw,
    const float* __restrict__ inw,  const float* __restrict__ outw,
    bf16* __restrict__ xh, bf16* __restrict__ xl,
    bf16* __restrict__ wch, bf16* __restrict__ wcl,
    bf16* __restrict__ wmh, bf16* __restrict__ wml,
    bf16* __restrict__ wih, bf16* __restrict__ wil,
    bf16* __restrict__ woh, bf16* __restrict__ wol)
{
    __shared__ float t[64][65];
    const int b = blockIdx.x;
    const int tid = threadIdx.x;

    if (b < 512) {
        const int hw0 = (b & 63) * 64, c0 = ((b >> 6) & 3) * 64, n = b >> 8;
        #pragma unroll
        for (int r = 0; r < 4; r++) {
            int c = (tid >> 4) + r * 16;
            float4 v = *(const float4*)&x[((size_t)n * C + c0 + c) * HW + hw0 + (tid & 15) * 4];
            t[c][(tid & 15) * 4 + 0] = v.x;
            t[c][(tid & 15) * 4 + 1] = v.y;
            t[c][(tid & 15) * 4 + 2] = v.z;
            t[c][(tid & 15) * 4 + 3] = v.w;
        }
        __syncthreads();
        const int hwl = tid >> 2, cq = (tid & 3) * 16;
        pk8 hb[2], lb[2];
        #pragma unroll
        for (int j = 0; j < 16; j++)
            split1(t[cq + j][hwl], hb[j >> 3].h[j & 7], lb[j >> 3].h[j & 7]);
        size_t base = ((size_t)n * HW + hw0 + hwl) * C + c0 + cq;
        *(uint4*)&xh[base] = hb[0].u; *(uint4*)&xh[base + 8] = hb[1].u;
        *(uint4*)&xl[base] = lb[0].u; *(uint4*)&xl[base + 8] = lb[1].u;
        return;
    }
    if (b < 768) {
        int row = b - 512;
        bf16 hh, ll; split1(conv1w[(size_t)row * C + tid], hh, ll);
        wch[(size_t)row * C + tid] = hh;
        wcl[(size_t)row * C + tid] = ll;
        return;
    }
    if (b < 1024) {
        int nrow = b - 768;
        float v = 0.f;
        if (nrow < 144)      v = offw[(size_t)tid * 144 + nrow];
        else if (nrow < 216) v = maskw[(size_t)tid * 72 + nrow - 144];
        bf16 hh, ll; split1(v, hh, ll);
        wmh[(size_t)nrow * C + tid] = hh;
        wml[(size_t)nrow * C + tid] = ll;
        return;
    }
    const float* Wk = (b < 1040) ? inw : outw;
    bf16* hi = (b < 1040) ? wih : woh;
    bf16* lo = (b < 1040) ? wil : wol;
    const int t4 = (b - 1024) & 15;
    const int k0 = (t4 & 3) * 64, n0 = (t4 >> 2) * 64;
    #pragma unroll
    for (int r = 0; r < 4; r++) {
        int k = k0 + (tid >> 4) + r * 16;
        float4 v = *(const float4*)&Wk[(size_t)k * C + n0 + (tid & 15) * 4];
        t[(tid & 15) * 4 + 0][k - k0] = v.x;
        t[(tid & 15) * 4 + 1][k - k0] = v.y;
        t[(tid & 15) * 4 + 2][k - k0] = v.z;
        t[(tid & 15) * 4 + 3][k - k0] = v.w;
    }
    __syncthreads();
    const int nl = tid >> 2, kq = (tid & 3) * 16;
    pk8 hb[2], lb[2];
    #pragma unroll
    for (int j = 0; j < 16; j++)
        split1(t[nl][kq + j], hb[j >> 3].h[j & 7], lb[j >> 3].h[j & 7]);
    size_t base = (size_t)(n0 + nl) * C + k0 + kq;
    *(uint4*)&hi[base] = hb[0].u; *(uint4*)&hi[base + 8] = hb[1].u;
    *(uint4*)&lo[base] = lb[0].u; *(uint4*)&lo[base + 8] = lb[1].u;
}

// ---------------------------------------------------------------------------
// Pipelined split-bf16 HMMA GEMM (R9 geometry): 64Mx128Nx32BK, 8 chunks.
// MODE 0: epi BN1+SiLU -> y planes.   MODE 1: +bias -> xproj fp16.
// MODE 2: +bias (216 guard) -> om.    MODE 3: bias+BN2+SiLU -> out NCHW fp32.
// ---------------------------------------------------------------------------
template<int MODE>
__global__ __launch_bounds__(256, 2)
void gemm_p(const bf16* __restrict__ Ah, const bf16* __restrict__ Al,
            const bf16* __restrict__ Bh, const bf16* __restrict__ Bl,
            const float* __restrict__ bias0, const float* __restrict__ bias1,
            const float* __restrict__ bg, const float* __restrict__ bb,
            const float* __restrict__ bm, const float* __restrict__ bv,
            float* __restrict__ outF, bf16* __restrict__ outHi, bf16* __restrict__ outLo)
{
    extern __shared__ char smem[];
    const uint32_t sb = smem_u32_of(smem);
    const int tid = threadIdx.x;
    const int lane = tid & 31, wid = tid >> 5;
    const int warpM = wid >> 2, warpN = wid & 3;
    const int bo = blockIdx.x * 128;
    const int bp = blockIdx.y * 64;

    auto issue = [&](int s, int chk) {
        const int c0b = chk * 64;
        const uint32_t stg = sb + s * STAGE_SZ;
        #pragma unroll
        for (int i = 0; i < 6; i++) {
            int id = tid + 256 * i;
            if (id < 512) {
                int pl = id >> 8, rem = id & 255, row = rem >> 2, q = rem & 3;
                const char* src = (const char*)(pl ? Al : Ah)
                                  + ((size_t)(bp + row) * C) * 2 + c0b + q * 16;
                cp16(stg + (pl ? OFF_ALO : OFF_AHI) + row * ROWB + q * 16, src);
            } else {
                int id2 = id - 512;
                int pl = id2 >> 9, rem = id2 & 511, row = rem >> 2, q = rem & 3;
                const char* src = (const char*)(pl ? Bl : Bh)
                                  + ((size_t)(bo + row) * C) * 2 + c0b + q * 16;
                cp16(stg + (pl ? OFF_BLO : OFF_BHI) + row * ROWB + q * 16, src);
            }
        }
        cp_commit();
    };

    float acc[2][4][4];
    #pragma unroll
    for (int mt = 0; mt < 2; mt++)
        #pragma unroll
        for (int nt = 0; nt < 4; nt++)
            #pragma unroll
            for (int q = 0; q < 4; q++) acc[mt][nt][q] = 0.f;

    const int lrow = lane & 15;
    const int lhalf = (lane >> 4) * 16;

    issue(0, 0);
    #pragma unroll 1
    for (int chk = 0; chk < 8; chk++) {
        if (chk < 7) { issue((chk + 1) & 1, chk + 1); cp_wait<1>(); }
        else         { cp_wait<0>(); }
        __syncthreads();
        const uint32_t stg = sb + (chk & 1) * STAGE_SZ;
        #pragma unroll
        for (int ks = 0; ks < 2; ks++) {
            const uint32_t kb = ks * 32 + lhalf;
            uint32_t aH[2][4], aL[2][4], bH[2][4], bL[2][4];
            #pragma unroll
            for (int mt = 0; mt < 2; mt++) {
                uint32_t r = (warpM * 32 + mt * 16 + lrow) * ROWB + kb;
                ldsm4(aH[mt], stg + OFF_AHI + r);
                ldsm4(aL[mt], stg + OFF_ALO + r);
            }
            #pragma unroll
            for (int ng = 0; ng < 2; ng++) {
                uint32_t r = (warpN * 32 + ng * 16 + lrow) * ROWB + kb;
                ldsm4(bH[ng], stg + OFF_BHI + r);
                ldsm4(bL[ng], stg + OFF_BLO + r);
            }
            #pragma unroll
            for (int mt = 0; mt < 2; mt++)
                #pragma unroll
                for (int nt = 0; nt < 4; nt++) {
                    const int ng = nt >> 1, hsel = nt & 1;
                    mma16816(acc[mt][nt], aH[mt], bH[ng][hsel], bH[ng][2 + hsel]);
                    mma16816(acc[mt][nt], aH[mt], bL[ng][hsel], bL[ng][2 + hsel]);
                    mma16816(acc[mt][nt], aL[mt], bH[ng][hsel], bH[ng][2 + hsel]);
                }
        }
        __syncthreads();
    }

    const int rql = lane >> 2;
    const int cql = (lane & 3) * 2;

    if (MODE == 0) {
        #pragma unroll
        for (int mt = 0; mt < 2; mt++) {
            int p0 = bp + warpM * 32 + mt * 16 + rql;
            #pragma unroll
            for (int nt = 0; nt < 4; nt++) {
                int o = bo + warpN * 32 + nt * 8 + cql;
                float s0 = bg[o] * rsqrtf(bv[o] + 1e-3f);
                float s1 = bg[o+1] * rsqrtf(bv[o+1] + 1e-3f);
                float b0 = bb[o] - bm[o] * s0;
                float b1 = bb[o+1] - bm[o+1] * s1;
                float e0 = silu(acc[mt][nt][0] * s0 + b0);
                float e1 = silu(acc[mt][nt][1] * s1 + b1);
                float e2 = silu(acc[mt][nt][2] * s0 + b0);
                float e3 = silu(acc[mt][nt][3] * s1 + b1);
                __nv_bfloat162 h01, l01, h23, l23;
                split1(e0, h01.x, l01.x); split1(e1, h01.y, l01.y);
                split1(e2, h23.x, l23.x); split1(e3, h23.y, l23.y);
                *(__nv_bfloat162*)&outHi[(size_t)p0 * C + o] = h01;
                *(__nv_bfloat162*)&outLo[(size_t)p0 * C + o] = l01;
                *(__nv_bfloat162*)&outHi[(size_t)(p0 + 8) * C + o] = h23;
                *(__nv_bfloat162*)&outLo[(size_t)(p0 + 8) * C + o] = l23;
            }
        }
    } else if (MODE == 1) {
        __half* outH = (__half*)outF;     // fp16 xproj
        #pragma unroll
        for (int mt = 0; mt < 2; mt++) {
            int p0 = bp + warpM * 32 + mt * 16 + rql;
            #pragma unroll
            for (int nt = 0; nt < 4; nt++) {
                int o = bo + warpN * 32 + nt * 8 + cql;
                float b0 = bias0[o], b1 = bias0[o + 1];
                *(__half2*)&outH[(size_t)p0 * C + o] =
                    __floats2half2_rn(acc[mt][nt][0] + b0, acc[mt][nt][1] + b1);
                *(__half2*)&outH[(size_t)(p0 + 8) * C + o] =
                    __floats2half2_rn(acc[mt][nt][2] + b0, acc[mt][nt][3] + b1);
            }
        }
    } else if (MODE == 2) {
        #pragma unroll
        for (int mt = 0; mt < 2; mt++) {
            int p0 = bp + warpM * 32 + mt * 16 + rql;
            #pragma unroll
            for (int nt = 0; nt < 4; nt++) {
                int o = bo + warpN * 32 + nt * 8 + cql;
                #pragma unroll
                for (int j = 0; j < 2; j++) {
                    int col = o + j;
                    if (col < OMC) {
                        float bi = (col < 144) ? bias0[col] : bias1[col - 144];
                        outF[(size_t)p0 * OMC + col]       = acc[mt][nt][j] + bi;
                        outF[(size_t)(p0 + 8) * OMC + col] = acc[mt][nt][2 + j] + bi;
                    }
                }
            }
        }
    } else {
        float* ts = (float*)smem;          // [128 o][68 p]
        #pragma unroll
        for (int mt = 0; mt < 2; mt++) {
            int r0 = warpM * 32 + mt * 16 + rql;
            #pragma unroll
            for (int nt = 0; nt < 4; nt++) {
                int c0t = warpN * 32 + nt * 8 + cql;
                ts[(size_t)c0t * 68 + r0]           = acc[mt][nt][0];
                ts[(size_t)(c0t + 1) * 68 + r0]     = acc[mt][nt][1];
                ts[(size_t)c0t * 68 + r0 + 8]       = acc[mt][nt][2];
                ts[(size_t)(c0t + 1) * 68 + r0 + 8] = acc[mt][nt][3];
            }
        }
        __syncthreads();
        const int n = bp >> 12, hwbase = bp & 4095;
        const int ol = tid >> 1, ph = (tid & 1) * 32;
        const int o = bo + ol;
        float sc = bg[o] * rsqrtf(bv[o] + 1e-5f);
        float bi = bb[o] - bm[o] * sc + bias0[o] * sc;
        float* op = &outF[((size_t)(n * C + o)) * HW + hwbase + ph];
        #pragma unroll
        for (int q = 0; q < 8; q++) {
            float v0 = silu(ts[(size_t)ol * 68 + ph + q * 4 + 0] * sc + bi);
            float v1 = silu(ts[(size_t)ol * 68 + ph + q * 4 + 1] * sc + bi);
            float v2 = silu(ts[(size_t)ol * 68 + ph + q * 4 + 2] * sc + bi);
            float v3 = silu(ts[(size_t)ol * 68 + ph + q * 4 + 3] * sc + bi);
            *(float4*)&op[q * 4] = make_float4(v0, v1, v2, v3);
        }
    }
}

// ---------------------------------------------------------------------------
// dwln v1 (proven): one block per pixel; depthwise 3x3 + LN + GELU
// ---------------------------------------------------------------------------
__global__ __launch_bounds__(256) void dwln_kernel(
    const bf16* __restrict__ yh, const bf16* __restrict__ yl,
    const float* __restrict__ dww, const float* __restrict__ dwb,
    const float* __restrict__ lng, const float* __restrict__ lnb,
    bf16* __restrict__ zh, bf16* __restrict__ zl)
{
    const int p = blockIdx.x;
    const int c = threadIdx.x;
    const int n = p >> 12, hw = p & 4095;
    const int h = hw >> 6, w = hw & 63;

    float acc = dwb[c];
    #pragma unroll
    for (int ky = 0; ky < 3; ky++) {
        int hh = h + ky - 1;
        if (hh < 0 || hh > 63) continue;
        #pragma unroll
        for (int kx = 0; kx < 3; kx++) {
            int ww = w + kx - 1;
            if (ww < 0 || ww > 63) continue;
            size_t idx = ((size_t)(n << 12) + (hh << 6) + ww) * C + c;
            float v = __bfloat162float(yh[idx]) + __bfloat162float(yl[idx]);
            acc += v * dww[c * 9 + ky * 3 + kx];
        }
    }
    float s1 = acc, s2 = acc * acc;
    #pragma unroll
    for (int o = 16; o; o >>= 1) {
        s1 += __shfl_xor_sync(0xffffffffu, s1, o);
        s2 += __shfl_xor_sync(0xffffffffu, s2, o);
    }
    __shared__ float w1[8], w2[8];
    int warp = c >> 5, lane = c & 31;
    if (lane == 0) { w1[warp] = s1; w2[warp] = s2; }
    __syncthreads();
    if (warp == 0) {
        float a = lane < 8 ? w1[lane] : 0.f;
        float b = lane < 8 ? w2[lane] : 0.f;
        #pragma unroll
        for (int o = 4; o; o >>= 1) {
            a += __shfl_xor_sync(0xffffffffu, a, o);
            b += __shfl_xor_sync(0xffffffffu, b, o);
        }
        if (lane == 0) { w1[0] = a; w2[0] = b; }
    }
    __syncthreads();
    float mu = w1[0] * (1.f / 256.f);
    float var = w2[0] * (1.f / 256.f) - mu * mu;
    float zn = (acc - mu) * rsqrtf(var + 1e-5f) * lng[c] + lnb[c];
    float gl = 0.5f * zn * (1.f + erff(zn * 0.70710678118654752f));
    bf16 hh2, ll2; split1(gl, hh2, ll2);
    zh[(size_t)p * C + c] = hh2;
    zl[(size_t)p * C + c] = ll2;
}

// ---------------------------------------------------------------------------
// deformable sampling; reads xproj fp16 + om fp32, writes s planes
// ---------------------------------------------------------------------------
__device__ __forceinline__ float samp(const __half* __restrict__ xb, int yy, int xx)
{
    if (yy >= 1 && yy <= 64 && xx >= 1 && xx <= 64)
        return __half2float(xb[((size_t)((yy - 1) << 6) + (xx - 1)) * C]);
    return 0.f;
}

__global__ __launch_bounds__(256) void dcn_kernel(
    const __half* __restrict__ xproj, const float* __restrict__ om,
    bf16* __restrict__ sh, bf16* __restrict__ sl)
{
    const int p = blockIdx.x;
    const int t = threadIdx.x;
    const int g = t >> 5, lane = t & 31;
    const int n = p >> 12, hw = p & 4095;
    const int h = hw >> 6, w = hw & 63;

    const float* offp = om + (size_t)p * OMC + g * 18;
    const float* mlp  = om + (size_t)p * OMC + 144 + g * 9;

    float ml[9];
    float mx = -1e30f;
    #pragma unroll
    for (int i = 0; i < 9; i++) { ml[i] = mlp[i]; mx = fmaxf(mx, ml[i]); }
    float se = 0.f;
    #pragma unroll
    for (int i = 0; i < 9; i++) { ml[i] = __expf(ml[i] - mx); se += ml[i]; }
    float inv = 1.f / se;

    const int ch = g * 32 + lane;
    const __half* xb = xproj + (size_t)n * HW * C + ch;
    float acc = 0.f;
    #pragma unroll
    for (int i = 0; i < 9; i++) {
        float px = (float)w + (float)(i / 3) + offp[2 * i];
        float py = (float)h + (float)(i % 3) + offp[2 * i + 1];
        float x0f = floorf(px), y0f = floorf(py);
        float wx = px - x0f, wy = py - y0f;
        int x0 = (int)x0f, y0 = (int)y0f;
        float v00 = samp(xb, y0,     x0);
        float v10 = samp(xb, y0,     x0 + 1);
        float v01 = samp(xb, y0 + 1, x0);
        float v11 = samp(xb, y0 + 1, x0 + 1);
        float bil = v00 * (1.f - wx) * (1.f - wy) + v10 * wx * (1.f - wy)
                  + v01 * (1.f - wx) * wy         + v11 * wx * wy;
        acc += ml[i] * inv * bil;
    }
    bf16 hh2, ll2; split1(acc, hh2, ll2);
    sh[(size_t)p * C + ch] = hh2;
    sl[(size_t)p * C + ch] = ll2;
}

// ---------------------------------------------------------------------------
extern "C" void kernel_launch(void* const* d_in, const int* in_sizes, int n_in,
                              void* d_out, int out_size)
{
    const float* x        = (const float*)d_in[0];
    const float* conv1_w  = (const float*)d_in[1];
    const float* bn1_g    = (const float*)d_in[2];
    const float* bn1_b    = (const float*)d_in[3];
    const float* bn1_m    = (const float*)d_in[4];
    const float* bn1_v    = (const float*)d_in[5];
    const float* inproj_w = (const float*)d_in[6];
    const float* inproj_b = (const float*)d_in[7];
    const float* dw_w     = (const float*)d_in[8];
    const float* dw_b     = (const float*)d_in[9];
    const float* ln_g     = (const float*)d_in[10];
    const float* ln_b     = (const float*)d_in[11];
    const float* off_w    = (const float*)d_in[12];
    const float* off_b    = (const float*)d_in[13];
    const float* mask_w   = (const float*)d_in[14];
    const float* mask_b   = (const float*)d_in[15];
    const float* outproj_w= (const float*)d_in[16];
    const float* outproj_b= (const float*)d_in[17];
    const float* bn2_g    = (const float*)d_in[18];
    const float* bn2_b    = (const float*)d_in[19];
    const float* bn2_m    = (const float*)d_in[20];
    const float* bn2_v    = (const float*)d_in[21];
    float* out = (float*)d_out;

    bf16 *xh, *xl, *yh, *yl, *zh, *zl, *sh, *sl;
    bf16 *wch, *wcl, *wih, *wil, *woh, *wol, *wmh, *wml;
    __half *xproj;
    float *om;
    cudaGetSymbolAddress((void**)&xh, g_xh); cudaGetSymbolAddress((void**)&xl, g_xl);
    cudaGetSymbolAddress((void**)&yh, g_yh); cudaGetSymbolAddress((void**)&yl, g_yl);
    cudaGetSymbolAddress((void**)&zh, g_zh); cudaGetSymbolAddress((void**)&zl, g_zl);
    cudaGetSymbolAddress((void**)&sh, g_sh); cudaGetSymbolAddress((void**)&sl, g_sl);
    cudaGetSymbolAddress((void**)&wch, g_wch); cudaGetSymbolAddress((void**)&wcl, g_wcl);
    cudaGetSymbolAddress((void**)&wih, g_wih); cudaGetSymbolAddress((void**)&wil, g_wil);
    cudaGetSymbolAddress((void**)&woh, g_woh); cudaGetSymbolAddress((void**)&wol, g_wol);
    cudaGetSymbolAddress((void**)&wmh, g_wmh); cudaGetSymbolAddress((void**)&wml, g_wml);
    cudaGetSymbolAddress((void**)&xproj, g_xproj);
    cudaGetSymbolAddress((void**)&om, g_om);

    cudaFuncSetAttribute(gemm_p<0>, cudaFuncAttributeMaxDynamicSharedMemorySize, SMEM_TOTAL);
    cudaFuncSetAttribute(gemm_p<1>, cudaFuncAttributeMaxDynamicSharedMemorySize, SMEM_TOTAL);
    cudaFuncSetAttribute(gemm_p<2>, cudaFuncAttributeMaxDynamicSharedMemorySize, SMEM_TOTAL);
    cudaFuncSetAttribute(gemm_p<3>, cudaFuncAttributeMaxDynamicSharedMemorySize, SMEM_TOTAL);

    // ---- prep (one launch) ----
    prep_fused<<<1056, 256>>>(x, conv1_w, off_w, mask_w, inproj_w, outproj_w,
                              xh, xl, wch, wcl, wmh, wml, wih, wil, woh, wol);

    dim3 grd(2, 128);
    // ---- pipeline (R9 structure) ----
    gemm_p<0><<<grd, 256, SMEM_TOTAL>>>(xh, xl, wch, wcl, nullptr, nullptr,
                                        bn1_g, bn1_b, bn1_m, bn1_v,
                                        nullptr, yh, yl);
    gemm_p<1><<<grd, 256, SMEM_TOTAL>>>(yh, yl, wih, wil, inproj_b, nullptr,
                                        nullptr, nullptr, nullptr, nullptr,
                                        (float*)xproj, nullptr, nullptr);
    dwln_kernel<<<M, 256>>>(yh, yl, dw_w, dw_b, ln_g, ln_b, zh, zl);
    gemm_p<2><<<grd, 256, SMEM_TOTAL>>>(zh, zl, wmh, wml, off_b, mask_b,
                                        nullptr, nullptr, nullptr, nullptr,
                                        om, nullptr, nullptr);
    dcn_kernel<<<M, 256>>>(xproj, om, sh, sl);
    gemm_p<3><<<grd, 256, SMEM_TOTAL>>>(sh, sl, woh, wol, outproj_b, nullptr,
                                        bn2_g, bn2_b, bn2_m, bn2_v,
                                        out, nullptr, nullptr);
}

// round 13
// speedup vs baseline: 1.1734x; 1.0274x over previous
#include <cuda_runtime.h>
#include <cuda_bf16.h>
#include <cuda_fp16.h>
#include <math.h>
#include <stdint.h>

#define NB   2
#define C    256
#define H    64
#define W    64
#define HW   4096
#define M    8192
#define G    8
#define P    9
#define CG   32
#define OMC  216

typedef __nv_bfloat16 bf16;

// ---- scratch (device globals) ----
__device__ __align__(16) bf16 g_xh[M * C];
__device__ __align__(16) bf16 g_xl[M * C];
__device__ __align__(16) bf16 g_yh[M * C];
__device__ __align__(16) bf16 g_yl[M * C];
__device__ __align__(16) float g_yf[M * C];         // fp32 y copy for dwln
__device__ __align__(16) bf16 g_zh[M * C];
__device__ __align__(16) bf16 g_zl[M * C];
__device__ __align__(16) bf16 g_sh[M * C];
__device__ __align__(16) bf16 g_sl[M * C];
__device__ __align__(16) __half g_xproj[M * C];     // fp16 (dcn is L2-BW-bound)
__device__ __align__(16) float g_om[M * OMC];
// weight planes, all [n-row][k] k-contig, 256x256
__device__ __align__(16) bf16 g_wch[C * C], g_wcl[C * C];   // conv1
__device__ __align__(16) bf16 g_wih[C * C], g_wil[C * C];   // inproj
__device__ __align__(16) bf16 g_woh[C * C], g_wol[C * C];   // outproj
__device__ __align__(16) bf16 g_wmh[C * C], g_wml[C * C];   // off|mask

__device__ __forceinline__ float silu(float t) { return t / (1.f + __expf(-t)); }

__device__ __forceinline__ uint32_t smem_u32_of(const void* p) {
    uint32_t a;
    asm("{ .reg .u64 t; cvta.to.shared.u64 t, %1; cvt.u32.u64 %0, t; }"
        : "=r"(a) : "l"(p));
    return a;
}
__device__ __forceinline__ void split1(float v, bf16& hi, bf16& lo) {
    hi = __float2bfloat16(v);
    lo = __float2bfloat16(v - __bfloat162float(hi));
}
__device__ __forceinline__ void ldsm4(uint32_t* r, uint32_t addr) {
    asm volatile("ldmatrix.sync.aligned.m8n8.x4.shared.b16 {%0,%1,%2,%3}, [%4];"
                 : "=r"(r[0]), "=r"(r[1]), "=r"(r[2]), "=r"(r[3]) : "r"(addr));
}
__device__ __forceinline__ void mma16816(float* c, const uint32_t* a, uint32_t b0, uint32_t b1) {
    asm volatile(
        "mma.sync.aligned.m16n8k16.row.col.f32.bf16.bf16.f32 "
        "{%0,%1,%2,%3}, {%4,%5,%6,%7}, {%8,%9}, {%0,%1,%2,%3};"
        : "+f"(c[0]), "+f"(c[1]), "+f"(c[2]), "+f"(c[3])
        : "r"(a[0]), "r"(a[1]), "r"(a[2]), "r"(a[3]), "r"(b0), "r"(b1));
}
__device__ __forceinline__ void cp16(uint32_t dst, const void* src) {
    asm volatile("cp.async.cg.shared.global [%0], [%1], 16;" :: "r"(dst), "l"(src));
}
__device__ __forceinline__ void cp_commit() {
    asm volatile("cp.async.commit_group;");
}
template<int N> __device__ __forceinline__ void cp_wait() {
    asm volatile("cp.async.wait_group %0;" :: "n"(N));
}

// SMEM: per stage bf16 planes, 80B padded rows (conflict-free ldmatrix).
// A: 64 rows (hi/lo), B: 128 rows (hi/lo)   (R9-proven geometry)
#define ROWB      80
#define OFF_AHI   0
#define OFF_ALO   (64 * ROWB)
#define OFF_BHI   (128 * ROWB)
#define OFF_BLO   (256 * ROWB)
#define STAGE_SZ  (384 * ROWB)          // 30720
#define SMEM_TOTAL (2 * STAGE_SZ)       // 61440

union pk8 { bf16 h[8]; uint4 u; };

// ---------------------------------------------------------------------------
// merged prep (R11-verified): blocks [0,512) x planes; [512,768) conv1;
// [768,1024) off|mask; [1024,1040) inproj tiles; [1040,1056) outproj tiles.
// ---------------------------------------------------------------------------
__global__ __launch_bounds__(256) void prep_fused(
    const float* __restrict__ x,
    const float* __restrict__ conv1w,
    const float* __restrict__ offw, const float* __restrict__ maskw,
    const float* __restrict__ inw,  const float* __restrict__ outw,
    bf16* __restrict__ xh, bf16* __restrict__ xl,
    bf16* __restrict__ wch, bf16* __restrict__ wcl,
    bf16* __restrict__ wmh, bf16* __restrict__ wml,
    bf16* __restrict__ wih, bf16* __restrict__ wil,
    bf16* __restrict__ woh, bf16* __restrict__ wol)
{
    __shared__ float t[64][65];
    const int b = blockIdx.x;
    const int tid = threadIdx.x;

    if (b < 512) {
        const int hw0 = (b & 63) * 64, c0 = ((b >> 6) & 3) * 64, n = b >> 8;
        #pragma unroll
        for (int r = 0; r < 4; r++) {
            int c = (tid >> 4) + r * 16;
            float4 v = *(const float4*)&x[((size_t)n * C + c0 + c) * HW + hw0 + (tid & 15) * 4];
            t[c][(tid & 15) * 4 + 0] = v.x;
            t[c][(tid & 15) * 4 + 1] = v.y;
            t[c][(tid & 15) * 4 + 2] = v.z;
            t[c][(tid & 15) * 4 + 3] = v.w;
        }
        __syncthreads();
        const int hwl = tid >> 2, cq = (tid & 3) * 16;
        pk8 hb[2], lb[2];
        #pragma unroll
        for (int j = 0; j < 16; j++)
            split1(t[cq + j][hwl], hb[j >> 3].h[j & 7], lb[j >> 3].h[j & 7]);
        size_t base = ((size_t)n * HW + hw0 + hwl) * C + c0 + cq;
        *(uint4*)&xh[base] = hb[0].u; *(uint4*)&xh[base + 8] = hb[1].u;
        *(uint4*)&xl[base] = lb[0].u; *(uint4*)&xl[base + 8] = lb[1].u;
        return;
    }
    if (b < 768) {
        int row = b - 512;
        bf16 hh, ll; split1(conv1w[(size_t)row * C + tid], hh, ll);
        wch[(size_t)row * C + tid] = hh;
        wcl[(size_t)row * C + tid] = ll;
        return;
    }
    if (b < 1024) {
        int nrow = b - 768;
        float v = 0.f;
        if (nrow < 144)      v = offw[(size_t)tid * 144 + nrow];
        else if (nrow < 216) v = maskw[(size_t)tid * 72 + nrow - 144];
        bf16 hh, ll; split1(v, hh, ll);
        wmh[(size_t)nrow * C + tid] = hh;
        wml[(size_t)nrow * C + tid] = ll;
        return;
    }
    const float* Wk = (b < 1040) ? inw : outw;
    bf16* hi = (b < 1040) ? wih : woh;
    bf16* lo = (b < 1040) ? wil : wol;
    const int t4 = (b - 1024) & 15;
    const int k0 = (t4 & 3) * 64, n0 = (t4 >> 2) * 64;
    #pragma unroll
    for (int r = 0; r < 4; r++) {
        int k = k0 + (tid >> 4) + r * 16;
        float4 v = *(const float4*)&Wk[(size_t)k * C + n0 + (tid & 15) * 4];
        t[(tid & 15) * 4 + 0][k - k0] = v.x;
        t[(tid & 15) * 4 + 1][k - k0] = v.y;
        t[(tid & 15) * 4 + 2][k - k0] = v.z;
        t[(tid & 15) * 4 + 3][k - k0] = v.w;
    }
    __syncthreads();
    const int nl = tid >> 2, kq = (tid & 3) * 16;
    pk8 hb[2], lb[2];
    #pragma unroll
    for (int j = 0; j < 16; j++)
        split1(t[nl][kq + j], hb[j >> 3].h[j & 7], lb[j >> 3].h[j & 7]);
    size_t base = (size_t)(n0 + nl) * C + k0 + kq;
    *(uint4*)&hi[base] = hb[0].u; *(uint4*)&hi[base + 8] = hb[1].u;
    *(uint4*)&lo[base] = lb[0].u; *(uint4*)&lo[base + 8] = lb[1].u;
}

// ---------------------------------------------------------------------------
// Pipelined split-bf16 HMMA GEMM (R9 geometry): 64Mx128Nx32BK, 8 chunks.
// MODE 0: epi BN1+SiLU -> y planes + fp32 y copy.  MODE 1: +bias -> xproj fp16.
// MODE 2: +bias (216 guard) -> om.  MODE 3: bias+BN2+SiLU -> out NCHW fp32.
// ---------------------------------------------------------------------------
template<int MODE>
__global__ __launch_bounds__(256, 2)
void gemm_p(const bf16* __restrict__ Ah, const bf16* __restrict__ Al,
            const bf16* __restrict__ Bh, const bf16* __restrict__ Bl,
            const float* __restrict__ bias0, const float* __restrict__ bias1,
            const float* __restrict__ bg, const float* __restrict__ bb,
            const float* __restrict__ bm, const float* __restrict__ bv,
            float* __restrict__ outF, bf16* __restrict__ outHi, bf16* __restrict__ outLo)
{
    extern __shared__ char smem[];
    const uint32_t sb = smem_u32_of(smem);
    const int tid = threadIdx.x;
    const int lane = tid & 31, wid = tid >> 5;
    const int warpM = wid >> 2, warpN = wid & 3;
    const int bo = blockIdx.x * 128;
    const int bp = blockIdx.y * 64;

    auto issue = [&](int s, int chk) {
        const int c0b = chk * 64;
        const uint32_t stg = sb + s * STAGE_SZ;
        #pragma unroll
        for (int i = 0; i < 6; i++) {
            int id = tid + 256 * i;
            if (id < 512) {
                int pl = id >> 8, rem = id & 255, row = rem >> 2, q = rem & 3;
                const char* src = (const char*)(pl ? Al : Ah)
                                  + ((size_t)(bp + row) * C) * 2 + c0b + q * 16;
                cp16(stg + (pl ? OFF_ALO : OFF_AHI) + row * ROWB + q * 16, src);
            } else {
                int id2 = id - 512;
                int pl = id2 >> 9, rem = id2 & 511, row = rem >> 2, q = rem & 3;
                const char* src = (const char*)(pl ? Bl : Bh)
                                  + ((size_t)(bo + row) * C) * 2 + c0b + q * 16;
                cp16(stg + (pl ? OFF_BLO : OFF_BHI) + row * ROWB + q * 16, src);
            }
        }
        cp_commit();
    };

    float acc[2][4][4];
    #pragma unroll
    for (int mt = 0; mt < 2; mt++)
        #pragma unroll
        for (int nt = 0; nt < 4; nt++)
            #pragma unroll
            for (int q = 0; q < 4; q++) acc[mt][nt][q] = 0.f;

    const int lrow = lane & 15;
    const int lhalf = (lane >> 4) * 16;

    issue(0, 0);
    #pragma unroll 1
    for (int chk = 0; chk < 8; chk++) {
        if (chk < 7) { issue((chk + 1) & 1, chk + 1); cp_wait<1>(); }
        else         { cp_wait<0>(); }
        __syncthreads();
        const uint32_t stg = sb + (chk & 1) * STAGE_SZ;
        #pragma unroll
        for (int ks = 0; ks < 2; ks++) {
            const uint32_t kb = ks * 32 + lhalf;
            uint32_t aH[2][4], aL[2][4], bH[2][4], bL[2][4];
            #pragma unroll
            for (int mt = 0; mt < 2; mt++) {
                uint32_t r = (warpM * 32 + mt * 16 + lrow) * ROWB + kb;
                ldsm4(aH[mt], stg + OFF_AHI + r);
                ldsm4(aL[mt], stg + OFF_ALO + r);
            }
            #pragma unroll
            for (int ng = 0; ng < 2; ng++) {
                uint32_t r = (warpN * 32 + ng * 16 + lrow) * ROWB + kb;
                ldsm4(bH[ng], stg + OFF_BHI + r);
                ldsm4(bL[ng], stg + OFF_BLO + r);
            }
            #pragma unroll
            for (int mt = 0; mt < 2; mt++)
                #pragma unroll
                for (int nt = 0; nt < 4; nt++) {
                    const int ng = nt >> 1, hsel = nt & 1;
                    mma16816(acc[mt][nt], aH[mt], bH[ng][hsel], bH[ng][2 + hsel]);
                    mma16816(acc[mt][nt], aH[mt], bL[ng][hsel], bL[ng][2 + hsel]);
                    mma16816(acc[mt][nt], aL[mt], bH[ng][hsel], bH[ng][2 + hsel]);
                }
        }
        __syncthreads();
    }

    const int rql = lane >> 2;
    const int cql = (lane & 3) * 2;

    if (MODE == 0) {
        #pragma unroll
        for (int mt = 0; mt < 2; mt++) {
            int p0 = bp + warpM * 32 + mt * 16 + rql;
            #pragma unroll
            for (int nt = 0; nt < 4; nt++) {
                int o = bo + warpN * 32 + nt * 8 + cql;
                float s0 = bg[o] * rsqrtf(bv[o] + 1e-3f);
                float s1 = bg[o+1] * rsqrtf(bv[o+1] + 1e-3f);
                float b0 = bb[o] - bm[o] * s0;
                float b1 = bb[o+1] - bm[o+1] * s1;
                float e0 = silu(acc[mt][nt][0] * s0 + b0);
                float e1 = silu(acc[mt][nt][1] * s1 + b1);
                float e2 = silu(acc[mt][nt][2] * s0 + b0);
                float e3 = silu(acc[mt][nt][3] * s1 + b1);
                __nv_bfloat162 h01, l01, h23, l23;
                split1(e0, h01.x, l01.x); split1(e1, h01.y, l01.y);
                split1(e2, h23.x, l23.x); split1(e3, h23.y, l23.y);
                *(__nv_bfloat162*)&outHi[(size_t)p0 * C + o] = h01;
                *(__nv_bfloat162*)&outLo[(size_t)p0 * C + o] = l01;
                *(__nv_bfloat162*)&outHi[(size_t)(p0 + 8) * C + o] = h23;
                *(__nv_bfloat162*)&outLo[(size_t)(p0 + 8) * C + o] = l23;
                // fp32 y copy for dwln
                *(float2*)&outF[(size_t)p0 * C + o]       = make_float2(e0, e1);
                *(float2*)&outF[(size_t)(p0 + 8) * C + o] = make_float2(e2, e3);
            }
        }
    } else if (MODE == 1) {
        __half* outH = (__half*)outF;     // fp16 xproj
        #pragma unroll
        for (int mt = 0; mt < 2; mt++) {
            int p0 = bp + warpM * 32 + mt * 16 + rql;
            #pragma unroll
            for (int nt = 0; nt < 4; nt++) {
                int o = bo + warpN * 32 + nt * 8 + cql;
                float b0 = bias0[o], b1 = bias0[o + 1];
                *(__half2*)&outH[(size_t)p0 * C + o] =
                    __floats2half2_rn(acc[mt][nt][0] + b0, acc[mt][nt][1] + b1);
                *(__half2*)&outH[(size_t)(p0 + 8) * C + o] =
                    __floats2half2_rn(acc[mt][nt][2] + b0, acc[mt][nt][3] + b1);
            }
        }
    } else if (MODE == 2) {
        #pragma unroll
        for (int mt = 0; mt < 2; mt++) {
            int p0 = bp + warpM * 32 + mt * 16 + rql;
            #pragma unroll
            for (int nt = 0; nt < 4; nt++) {
                int o = bo + warpN * 32 + nt * 8 + cql;
                #pragma unroll
                for (int j = 0; j < 2; j++) {
                    int col = o + j;
                    if (col < OMC) {
                        float bi = (col < 144) ? bias0[col] : bias1[col - 144];
                        outF[(size_t)p0 * OMC + col]       = acc[mt][nt][j] + bi;
                        outF[(size_t)(p0 + 8) * OMC + col] = acc[mt][nt][2 + j] + bi;
                    }
                }
            }
        }
    } else {
        float* ts = (float*)smem;          // [128 o][68 p]
        #pragma unroll
        for (int mt = 0; mt < 2; mt++) {
            int r0 = warpM * 32 + mt * 16 + rql;
            #pragma unroll
            for (int nt = 0; nt < 4; nt++) {
                int c0t = warpN * 32 + nt * 8 + cql;
                ts[(size_t)c0t * 68 + r0]           = acc[mt][nt][0];
                ts[(size_t)(c0t + 1) * 68 + r0]     = acc[mt][nt][1];
                ts[(size_t)c0t * 68 + r0 + 8]       = acc[mt][nt][2];
                ts[(size_t)(c0t + 1) * 68 + r0 + 8] = acc[mt][nt][3];
            }
        }
        __syncthreads();
        const int n = bp >> 12, hwbase = bp & 4095;
        const int ol = tid >> 1, ph = (tid & 1) * 32;
        const int o = bo + ol;
        float sc = bg[o] * rsqrtf(bv[o] + 1e-5f);
        float bi = bb[o] - bm[o] * sc + bias0[o] * sc;
        float* op = &outF[((size_t)(n * C + o)) * HW + hwbase + ph];
        #pragma unroll
        for (int q = 0; q < 8; q++) {
            float v0 = silu(ts[(size_t)ol * 68 + ph + q * 4 + 0] * sc + bi);
            float v1 = silu(ts[(size_t)ol * 68 + ph + q * 4 + 1] * sc + bi);
            float v2 = silu(ts[(size_t)ol * 68 + ph + q * 4 + 2] * sc + bi);
            float v3 = silu(ts[(size_t)ol * 68 + ph + q * 4 + 3] * sc + bi);
            *(float4*)&op[q * 4] = make_float4(v0, v1, v2, v3);
        }
    }
}

// ---------------------------------------------------------------------------
// dwln v3: one block per pixel; reads fp32 y copy (1 load/tap, no CVT)
// ---------------------------------------------------------------------------
__global__ __launch_bounds__(256) void dwln_kernel(
    const float* __restrict__ yf,
    const float* __restrict__ dww, const float* __restrict__ dwb,
    const float* __restrict__ lng, const float* __restrict__ lnb,
    bf16* __restrict__ zh, bf16* __restrict__ zl)
{
    const int p = blockIdx.x;
    const int c = threadIdx.x;
    const int n = p >> 12, hw = p & 4095;
    const int h = hw >> 6, w = hw & 63;

    const float* yb = yf + ((size_t)(n << 12)) * C + c;
    float acc = dwb[c];
    #pragma unroll
    for (int ky = 0; ky < 3; ky++) {
        int hh = h + ky - 1;
        if (hh < 0 || hh > 63) continue;
        #pragma unroll
        for (int kx = 0; kx < 3; kx++) {
            int ww = w + kx - 1;
            if (ww < 0 || ww > 63) continue;
            acc += yb[(size_t)((hh << 6) + ww) * C] * dww[c * 9 + ky * 3 + kx];
        }
    }
    float s1 = acc, s2 = acc * acc;
    #pragma unroll
    for (int o = 16; o; o >>= 1) {
        s1 += __shfl_xor_sync(0xffffffffu, s1, o);
        s2 += __shfl_xor_sync(0xffffffffu, s2, o);
    }
    __shared__ float w1[8], w2[8];
    int warp = c >> 5, lane = c & 31;
    if (lane == 0) { w1[warp] = s1; w2[warp] = s2; }
    __syncthreads();
    if (warp == 0) {
        float a = lane < 8 ? w1[lane] : 0.f;
        float b = lane < 8 ? w2[lane] : 0.f;
        #pragma unroll
        for (int o = 4; o; o >>= 1) {
            a += __shfl_xor_sync(0xffffffffu, a, o);
            b += __shfl_xor_sync(0xffffffffu, b, o);
        }
        if (lane == 0) { w1[0] = a; w2[0] = b; }
    }
    __syncthreads();
    float mu = w1[0] * (1.f / 256.f);
    float var = w2[0] * (1.f / 256.f) - mu * mu;
    float zn = (acc - mu) * rsqrtf(var + 1e-5f) * lng[c] + lnb[c];
    float gl = 0.5f * zn * (1.f + erff(zn * 0.70710678118654752f));
    bf16 hh2, ll2; split1(gl, hh2, ll2);
    zh[(size_t)p * C + c] = hh2;
    zl[(size_t)p * C + c] = ll2;
}

// ---------------------------------------------------------------------------
// deformable sampling; reads xproj fp16 + om fp32, writes s planes
// ---------------------------------------------------------------------------
__device__ __forceinline__ float samp(const __half* __restrict__ xb, int yy, int xx)
{
    if (yy >= 1 && yy <= 64 && xx >= 1 && xx <= 64)
        return __half2float(xb[((size_t)((yy - 1) << 6) + (xx - 1)) * C]);
    return 0.f;
}

__global__ __launch_bounds__(256) void dcn_kernel(
    const __half* __restrict__ xproj, const float* __restrict__ om,
    bf16* __restrict__ sh, bf16* __restrict__ sl)
{
    const int p = blockIdx.x;
    const int t = threadIdx.x;
    const int g = t >> 5, lane = t & 31;
    const int n = p >> 12, hw = p & 4095;
    const int h = hw >> 6, w = hw & 63;

    const float* offp = om + (size_t)p * OMC + g * 18;
    const float* mlp  = om + (size_t)p * OMC + 144 + g * 9;

    float ml[9];
    float mx = -1e30f;
    #pragma unroll
    for (int i = 0; i < 9; i++) { ml[i] = mlp[i]; mx = fmaxf(mx, ml[i]); }
    float se = 0.f;
    #pragma unroll
    for (int i = 0; i < 9; i++) { ml[i] = __expf(ml[i] - mx); se += ml[i]; }
    float inv = 1.f / se;

    const int ch = g * 32 + lane;
    const __half* xb = xproj + (size_t)n * HW * C + ch;
    float acc = 0.f;
    #pragma unroll
    for (int i = 0; i < 9; i++) {
        float px = (float)w + (float)(i / 3) + offp[2 * i];
        float py = (float)h + (float)(i % 3) + offp[2 * i + 1];
        float x0f = floorf(px), y0f = floorf(py);
        float wx = px - x0f, wy = py - y0f;
        int x0 = (int)x0f, y0 = (int)y0f;
        float v00 = samp(xb, y0,     x0);
        float v10 = samp(xb, y0,     x0 + 1);
        float v01 = samp(xb, y0 + 1, x0);
        float v11 = samp(xb, y0 + 1, x0 + 1);
        float bil = v00 * (1.f - wx) * (1.f - wy) + v10 * wx * (1.f - wy)
                  + v01 * (1.f - wx) * wy         + v11 * wx * wy;
        acc += ml[i] * inv * bil;
    }
    bf16 hh2, ll2; split1(acc, hh2, ll2);
    sh[(size_t)p * C + ch] = hh2;
    sl[(size_t)p * C + ch] = ll2;
}

// ---------------------------------------------------------------------------
extern "C" void kernel_launch(void* const* d_in, const int* in_sizes, int n_in,
                              void* d_out, int out_size)
{
    const float* x        = (const float*)d_in[0];
    const float* conv1_w  = (const float*)d_in[1];
    const float* bn1_g    = (const float*)d_in[2];
    const float* bn1_b    = (const float*)d_in[3];
    const float* bn1_m    = (const float*)d_in[4];
    const float* bn1_v    = (const float*)d_in[5];
    const float* inproj_w = (const float*)d_in[6];
    const float* inproj_b = (const float*)d_in[7];
    const float* dw_w     = (const float*)d_in[8];
    const float* dw_b     = (const float*)d_in[9];
    const float* ln_g     = (const float*)d_in[10];
    const float* ln_b     = (const float*)d_in[11];
    const float* off_w    = (const float*)d_in[12];
    const float* off_b    = (const float*)d_in[13];
    const float* mask_w   = (const float*)d_in[14];
    const float* mask_b   = (const float*)d_in[15];
    const float* outproj_w= (const float*)d_in[16];
    const float* outproj_b= (const float*)d_in[17];
    const float* bn2_g    = (const float*)d_in[18];
    const float* bn2_b    = (const float*)d_in[19];
    const float* bn2_m    = (const float*)d_in[20];
    const float* bn2_v    = (const float*)d_in[21];
    float* out = (float*)d_out;

    bf16 *xh, *xl, *yh, *yl, *zh, *zl, *sh, *sl;
    bf16 *wch, *wcl, *wih, *wil, *woh, *wol, *wmh, *wml;
    __half *xproj;
    float *om, *yf;
    cudaGetSymbolAddress((void**)&xh, g_xh); cudaGetSymbolAddress((void**)&xl, g_xl);
    cudaGetSymbolAddress((void**)&yh, g_yh); cudaGetSymbolAddress((void**)&yl, g_yl);
    cudaGetSymbolAddress((void**)&zh, g_zh); cudaGetSymbolAddress((void**)&zl, g_zl);
    cudaGetSymbolAddress((void**)&sh, g_sh); cudaGetSymbolAddress((void**)&sl, g_sl);
    cudaGetSymbolAddress((void**)&wch, g_wch); cudaGetSymbolAddress((void**)&wcl, g_wcl);
    cudaGetSymbolAddress((void**)&wih, g_wih); cudaGetSymbolAddress((void**)&wil, g_wil);
    cudaGetSymbolAddress((void**)&woh, g_woh); cudaGetSymbolAddress((void**)&wol, g_wol);
    cudaGetSymbolAddress((void**)&wmh, g_wmh); cudaGetSymbolAddress((void**)&wml, g_wml);
    cudaGetSymbolAddress((void**)&xproj, g_xproj);
    cudaGetSymbolAddress((void**)&om, g_om);
    cudaGetSymbolAddress((void**)&yf, g_yf);

    cudaFuncSetAttribute(gemm_p<0>, cudaFuncAttributeMaxDynamicSharedMemorySize, SMEM_TOTAL);
    cudaFuncSetAttribute(gemm_p<1>, cudaFuncAttributeMaxDynamicSharedMemorySize, SMEM_TOTAL);
    cudaFuncSetAttribute(gemm_p<2>, cudaFuncAttributeMaxDynamicSharedMemorySize, SMEM_TOTAL);
    cudaFuncSetAttribute(gemm_p<3>, cudaFuncAttributeMaxDynamicSharedMemorySize, SMEM_TOTAL);

    // ---- prep (one launch) ----
    prep_fused<<<1056, 256>>>(x, conv1_w, off_w, mask_w, inproj_w, outproj_w,
                              xh, xl, wch, wcl, wmh, wml, wih, wil, woh, wol);

    dim3 grd(2, 128);
    // ---- pipeline (R9 structure) ----
    gemm_p<0><<<grd, 256, SMEM_TOTAL>>>(xh, xl, wch, wcl, nullptr, nullptr,
                                        bn1_g, bn1_b, bn1_m, bn1_v,
                                        yf, yh, yl);
    gemm_p<1><<<grd, 256, SMEM_TOTAL>>>(yh, yl, wih, wil, inproj_b, nullptr,
                                        nullptr, nullptr, nullptr, nullptr,
                                        (float*)xproj, nullptr, nullptr);
    dwln_kernel<<<M, 256>>>(yf, dw_w, dw_b, ln_g, ln_b, zh, zl);
    gemm_p<2><<<grd, 256, SMEM_TOTAL>>>(zh, zl, wmh, wml, off_b, mask_b,
                                        nullptr, nullptr, nullptr, nullptr,
                                        om, nullptr, nullptr);
    dcn_kernel<<<M, 256>>>(xproj, om, sh, sl);
    gemm_p<3><<<grd, 256, SMEM_TOTAL>>>(sh, sl, woh, wol, outproj_b, nullptr,
                                        bn2_g, bn2_b, bn2_m, bn2_v,
                                        out, nullptr, nullptr);
}